// round 15
// baseline (speedup 1.0000x reference)
#include <cuda_runtime.h>
#include <cuda_bf16.h>
#include <cuda_fp16.h>
#include <cstdint>

#define Bb 32
#define Ss 128
#define Tt 128
#define DEMB 128
#define DENC 256
#define DDEC 512
#define Vv 32000
#define EKS 2
#define DKS 4
#define ESLOT (4*DENC*32)      // 32768 floats per enc partial slot
#define EHALF (2*EKS*ESLOT)    // 131072 floats per parity half
#define DSLOT (4*DDEC*32)      // 65536
#define DHALF (DKS*DSLOT)      // 262144

// ---------------- scratch (device globals; no runtime allocation) ----------------
__device__ float d_embS [Ss*Bb*DEMB];
__device__ float d_decin[Tt*Bb*DEMB];
__device__ float d_XGf  [Ss*Bb*4*DENC];        // TRANSPOSED: [t][n(1024)][b]
__device__ float d_XGb  [Ss*Bb*4*DENC];
__device__ float d_XGd  [Tt*Bb*4*DDEC];        // [t][n(2048)][b]
__device__ float d_hf   [(Ss+1)*Bb*DENC];      // [t][b][j]
__device__ float d_hb   [(Ss+1)*Bb*DENC];
__device__ float d_cf   [2*Bb*DENC];           // j-major: [buf][j*32+b]
__device__ float d_cb   [2*Bb*DENC];
__device__ float d_encpart[2*EHALF];           // [parity][dir*EKS+ks][n][b]
__device__ float d_mem  [Bb*Ss*2*DENC];
__device__ float d_ccat [Bb*2*DENC];
__device__ float d_H    [(Tt+1)*Bb*DDEC];
__device__ float d_cd   [2*Bb*DDEC];           // j-major
__device__ float d_decpart[2*DHALF];           // parity halves; half0 front reused by ct path
__device__ float d_FFN  [Tt*Bb*2*DDEC];
__device__ float d_HID  [Tt*Bb*DDEC];
// fp16 operands for tensor-core F2
__device__ __half d_Wf16 [Vv*DDEC];
__device__ __half d_HIDH [Tt*Bb*DDEC];

// ---------------- helpers ----------------
__device__ __forceinline__ float lrelu_f(float x){ return x >= 0.f ? x : 0.1f*x; }
__device__ __forceinline__ float sigm_f (float x){ return 1.f/(1.f+__expf(-x)); }
__device__ __forceinline__ float tanh_f (float x){
    float ax = fabsf(x);
    float e  = __expf(-2.f*ax);
    float r  = (1.f-e)/(1.f+e);
    return x >= 0.f ? r : -r;
}
#define CELL1(G0,G1,G2,G3,CO,CN,HN) { \
    float i_=sigm_f(G0), f_=sigm_f(G1), gg_=tanh_f(G2), o_=sigm_f(G3); \
    CN = f_*(CO) + i_*gg_; HN = o_*tanh_f(CN); }
__device__ __forceinline__ unsigned long long dup2(float a){
    unsigned long long r;
    asm("mov.b64 %0, {%1, %1};" : "=l"(r) : "f"(a));
    return r;
}
__device__ __forceinline__ void fma2(unsigned long long &c, unsigned long long a, unsigned long long w){
    asm("fma.rn.f32x2 %0, %1, %2, %0;" : "+l"(c) : "l"(a), "l"(w));
}
union F4U { float4 f; unsigned long long u[2]; };
union U64F2 { unsigned long long u; float2 f; };

__device__ __forceinline__ uint32_t smem_u32(const void* p){
    uint32_t a; asm("{ .reg .u64 t; cvta.to.shared.u64 t, %1; cvt.u32.u64 %0, t; }" : "=r"(a) : "l"(p));
    return a;
}
__device__ __forceinline__ void cp16(uint32_t saddr, const void* gaddr){
    asm volatile("cp.async.cg.shared.global [%0], [%1], 16;" :: "r"(saddr), "l"(gaddr));
}
__device__ __forceinline__ void ldm_x4(uint32_t addr, uint32_t &r0, uint32_t &r1, uint32_t &r2, uint32_t &r3){
    asm volatile("ldmatrix.sync.aligned.m8n8.x4.shared.b16 {%0,%1,%2,%3}, [%4];"
                 : "=r"(r0), "=r"(r1), "=r"(r2), "=r"(r3) : "r"(addr));
}
__device__ __forceinline__ void mma16816h(float* c, uint32_t a0, uint32_t a1, uint32_t a2, uint32_t a3,
                                          uint32_t b0, uint32_t b1){
    asm volatile("mma.sync.aligned.m16n8k16.row.col.f32.f16.f16.f32 "
                 "{%0,%1,%2,%3}, {%4,%5,%6,%7}, {%8,%9}, {%0,%1,%2,%3};"
                 : "+f"(c[0]), "+f"(c[1]), "+f"(c[2]), "+f"(c[3])
                 : "r"(a0), "r"(a1), "r"(a2), "r"(a3), "r"(b0), "r"(b1));
}

// ---------------- prep kernels ----------------
__global__ void p_emb(const int* __restrict__ inp, const float* __restrict__ tok_emb){
    int idx = blockIdx.x*256 + threadIdx.x;
    int sb = idx >> 7, d = idx & 127;
    int s = sb >> 5, b = sb & 31;
    d_embS[idx] = tok_emb[inp[b*Ss + s]*DEMB + d];
}
__global__ void p_decin(const int* __restrict__ x, const float* __restrict__ tok_emb,
                        const float* __restrict__ start_emb){
    int idx = blockIdx.x*256 + threadIdx.x;
    int tb = idx >> 7, d = idx & 127;
    int t = tb >> 5, b = tb & 31;
    d_decin[idx] = (t == 0) ? start_emb[d] : tok_emb[x[b*Tt + (t-1)]*DEMB + d];
}
__global__ void p_init(const int* __restrict__ label_i, const int* __restrict__ label,
                       const float* __restrict__ enc_style_emb, const float* __restrict__ style_emb){
    int idx = blockIdx.x*256 + threadIdx.x;
    if (idx < 16384){
        int dir = idx >> 13, r = idx & 8191;
        int b = r >> 8, j = r & 255;
        float v = enc_style_emb[label_i[b]*(2*DENC) + dir*DENC + j];
        (dir ? d_hb : d_hf)[b*DENC + j] = v;
    } else if (idx < 32768){
        int r = idx - 16384;
        int dir = r >> 13; r &= 8191;
        (dir ? d_cb : d_cf)[r] = 0.f;
    } else {
        int r = idx - 32768;
        int b = r >> 9, j = r & 511;
        d_H[b*DDEC + j] = style_emb[label[b]*DDEC + j];
    }
}
__global__ void conv_w16(const float* __restrict__ src, __half* __restrict__ dst, int n){
    int i = blockIdx.x*256 + threadIdx.x;
    if (i < n) dst[i] = __float2half_rn(src[i]);
}

// ---------------- fp32 GEMM (XG / F1): C = A @ W^T ----------------
// remapC=1 stores transposed per 32-row block: C[((m>>5)*N + n)*32 + (m&31)]
__global__ void __launch_bounds__(256) gemm_nt(
    const float* __restrict__ A, const float* __restrict__ W, float* __restrict__ C,
    int M, int N, int K,
    const float* __restrict__ bias1, const float* __restrict__ bias2,
    int act, int remapA, int remapC)
{
    __shared__ float As[8][128];
    __shared__ float Bs[8][128];
    int tid = threadIdx.x;
    int bm = blockIdx.y * 128, bn = blockIdx.x * 128;
    int lr = tid >> 1;
    int lc = (tid & 1) << 2;
    int arow = bm + lr;
    if (remapA) arow = ((Ss-1 - (arow >> 5)) << 5) | (arow & 31);
    const float* Aptr = A + arow*K + lc;
    const float* Wptr = W + (bn + lr)*K + lc;

    int m0 = (tid >> 4) << 3;
    int n0 = (tid & 15) << 3;
    unsigned long long acc[8][4];
#pragma unroll
    for (int i=0;i<8;i++)
#pragma unroll
        for (int j=0;j<4;j++) acc[i][j] = 0ull;

    for (int k0 = 0; k0 < K; k0 += 8){
        float4 a4 = *(const float4*)(Aptr + k0);
        float4 w4 = *(const float4*)(Wptr + k0);
        As[lc+0][lr]=a4.x; As[lc+1][lr]=a4.y; As[lc+2][lr]=a4.z; As[lc+3][lr]=a4.w;
        Bs[lc+0][lr]=w4.x; Bs[lc+1][lr]=w4.y; Bs[lc+2][lr]=w4.z; Bs[lc+3][lr]=w4.w;
        __syncthreads();
#pragma unroll
        for (int kk=0; kk<8; kk++){
            float4 a0 = *(const float4*)&As[kk][m0];
            float4 a1 = *(const float4*)&As[kk][m0+4];
            F4U ub0, ub1;
            ub0.f = *(const float4*)&Bs[kk][n0];
            ub1.f = *(const float4*)&Bs[kk][n0+4];
            unsigned long long w0=ub0.u[0], w1=ub0.u[1], w2=ub1.u[0], w3=ub1.u[1];
            float av[8] = {a0.x,a0.y,a0.z,a0.w,a1.x,a1.y,a1.z,a1.w};
#pragma unroll
            for (int i=0;i<8;i++){
                unsigned long long ad = dup2(av[i]);
                fma2(acc[i][0], ad, w0);
                fma2(acc[i][1], ad, w1);
                fma2(acc[i][2], ad, w2);
                fma2(acc[i][3], ad, w3);
            }
        }
        __syncthreads();
    }
#pragma unroll
    for (int i=0;i<8;i++){
        int mg = bm + m0 + i;
#pragma unroll
        for (int j=0;j<4;j++){
            U64F2 u; u.u = acc[i][j];
            float2 v = u.f;
            int ng = bn + n0 + 2*j;
            if (bias1){ v.x += bias1[ng]; v.y += bias1[ng+1]; }
            if (bias2){ v.x += bias2[ng]; v.y += bias2[ng+1]; }
            if (act){ v.x = lrelu_f(v.x); v.y = lrelu_f(v.y); }
            if (remapC){
                int base = ((mg>>5)*N + ng)*32 + (mg&31);
                C[base] = v.x; C[base + 32] = v.y;
            } else {
                *(float2*)&C[mg*N + ng] = v;
            }
        }
    }
}

// ---------------- mma.sync fp16 single-pass F2 GEMM ----------------
#define F2_NCHUNK 16
#define F2_ASTG   (128*40*2)
#define F2_BSTG   (256*40*2)
#define F2_STG    (F2_ASTG + F2_BSTG)
#define F2_SMEM   (3*F2_STG)
__global__ void __launch_bounds__(256) f2_mma(
    const __half* __restrict__ AH, const __half* __restrict__ Bg, float* __restrict__ out)
{
    extern __shared__ __half sm[];
    int tid = threadIdx.x;
    int wid = tid >> 5, lane = tid & 31;
    int warp_m = wid & 1, warp_n = wid >> 1;
    int bm = blockIdx.x * 128;
    int bn = blockIdx.y * 256;
    uint32_t sbase = smem_u32(sm);

    float acc[4][8][4];
#pragma unroll
    for (int i=0;i<4;i++)
#pragma unroll
        for (int j=0;j<8;j++)
#pragma unroll
            for (int q=0;q<4;q++) acc[i][j][q] = 0.f;

    auto load_chunk = [&](int c, int s){
        int k0 = c * 32;
        uint32_t base = sbase + (uint32_t)s * F2_STG;
#pragma unroll
        for (int q=0; q<2; q++){
            int i = q*256 + tid;
            int row = i >> 2, sg = i & 3;
            cp16(base + (uint32_t)(row*80 + sg*16), AH + (size_t)(bm + row)*DDEC + k0 + sg*8);
        }
#pragma unroll
        for (int q=0; q<4; q++){
            int i = q*256 + tid;
            int row = i >> 2, sg = i & 3;
            cp16(base + F2_ASTG + (uint32_t)(row*80 + sg*16),
                 Bg + (size_t)(bn + row)*DDEC + k0 + sg*8);
        }
        asm volatile("cp.async.commit_group;" ::: "memory");
    };

    load_chunk(0, 0);
    load_chunk(1, 1);

    int ld_s = 2, cs = 0;
    for (int c = 0; c < F2_NCHUNK; c++){
        if (c < F2_NCHUNK-1) asm volatile("cp.async.wait_group 1;" ::: "memory");
        else                 asm volatile("cp.async.wait_group 0;" ::: "memory");
        __syncthreads();
        if (c + 2 < F2_NCHUNK){
            load_chunk(c+2, ld_s);
            ld_s++; if (ld_s == 3) ld_s = 0;
        }
        uint32_t baseA = sbase + (uint32_t)cs * F2_STG;
        uint32_t baseB = baseA + F2_ASTG;
#pragma unroll
        for (int ks = 0; ks < 2; ks++){
            int kc = ks * 16;
            int g = lane >> 3, r = lane & 7;
            uint32_t af[4][4];
#pragma unroll
            for (int mt=0; mt<4; mt++){
                int row = warp_m*64 + mt*16 + (g & 1)*8 + r;
                int col = kc + (g >> 1)*8;
                ldm_x4(baseA + (uint32_t)(row*80 + col*2), af[mt][0], af[mt][1], af[mt][2], af[mt][3]);
            }
            uint32_t bf[8][2];
#pragma unroll
            for (int j=0; j<4; j++){
                int nrow = warp_n*64 + (j*2 + (g >> 1))*8 + r;
                int col = kc + (g & 1)*8;
                ldm_x4(baseB + (uint32_t)(nrow*80 + col*2),
                       bf[j*2][0], bf[j*2][1], bf[j*2+1][0], bf[j*2+1][1]);
            }
#pragma unroll
            for (int mt=0; mt<4; mt++)
#pragma unroll
                for (int nt=0; nt<8; nt++)
                    mma16816h(acc[mt][nt], af[mt][0], af[mt][1], af[mt][2], af[mt][3],
                              bf[nt][0], bf[nt][1]);
        }
        __syncthreads();
        cs++; if (cs == 3) cs = 0;
    }

#pragma unroll
    for (int mt=0; mt<4; mt++){
#pragma unroll
        for (int half=0; half<2; half++){
            int mg = bm + warp_m*64 + mt*16 + (lane >> 2) + half*8;
            int t = mg >> 5, b = mg & 31;
            float* dst = out + (size_t)(b*Tt + t)*Vv + bn + warp_n*64;
#pragma unroll
            for (int nt=0; nt<8; nt++){
                float2 v;
                v.x = acc[mt][nt][half*2+0];
                v.y = acc[mt][nt][half*2+1];
                *(float2*)&dst[nt*8 + 2*(lane & 3)] = v;
            }
        }
    }
}

// ---------------- fused encoder step: prologue cell (redundant) + K-split GEMM ----
// grid (16 nblk, EKS, 2 dir), 128 thr. Partials double-buffered by parity of t.
__global__ void __launch_bounds__(128) enc_fused(
    const float* __restrict__ Whh_f, const float* __restrict__ Whh_b, int t)
{
    __shared__ float hsm[128][36];
    __shared__ float Ws[32][68];
    int tid = threadIdx.x;
    int nblk = blockIdx.x, ks = blockIdx.y, dir = blockIdx.z;
    int kbase = ks*128;
    const float* W   = dir ? Whh_b : Whh_f;
    float* hbuf      = dir ? d_hb  : d_hf;
    const float* XGt = dir ? d_XGb : d_XGf;
    float* cbuf      = dir ? d_cb  : d_cf;

    if (t == 0){
#pragma unroll
        for (int q = 0; q < 8; q++){
            int i = tid + q*128;
            int b = i >> 5, j4 = i & 31;
            float4 v = *(const float4*)(hbuf + b*DENC + kbase + j4*4);
            hsm[j4*4+0][b]=v.x; hsm[j4*4+1][b]=v.y; hsm[j4*4+2][b]=v.z; hsm[j4*4+3][b]=v.w;
        }
    } else {
        const float* partr = d_encpart + ((t-1)&1)*EHALF + dir*EKS*ESLOT;
        int b0 = (tid & 7)*4, jr0 = (tid >> 3)*8;
#pragma unroll
        for (int jj = 0; jj < 8; jj++){
            int j = jr0 + jj, jg = kbase + j;
            float4 gs[4];
#pragma unroll
            for (int gt = 0; gt < 4; gt++){
                float4 v = *(const float4*)(XGt + ((size_t)(t-1)*(4*DENC) + gt*DENC + jg)*32 + b0);
#pragma unroll
                for (int k2 = 0; k2 < EKS; k2++){
                    float4 p = *(const float4*)(partr + k2*ESLOT + (gt*DENC + jg)*32 + b0);
                    v.x += p.x; v.y += p.y; v.z += p.z; v.w += p.w;
                }
                gs[gt] = v;
            }
            float4 co = *(const float4*)(cbuf + ((t-1)&1)*(Bb*DENC) + jg*32 + b0);
            float4 cn, hn;
            CELL1(gs[0].x, gs[1].x, gs[2].x, gs[3].x, co.x, cn.x, hn.x);
            CELL1(gs[0].y, gs[1].y, gs[2].y, gs[3].y, co.y, cn.y, hn.y);
            CELL1(gs[0].z, gs[1].z, gs[2].z, gs[3].z, co.z, cn.z, hn.z);
            CELL1(gs[0].w, gs[1].w, gs[2].w, gs[3].w, co.w, cn.w, hn.w);
            *(float4*)(cbuf + (t&1)*(Bb*DENC) + jg*32 + b0) = cn;
            *(float4*)&hsm[j][b0] = hn;
            if (nblk == 0){
                hbuf[(size_t)t*(Bb*DENC) + (b0+0)*DENC + jg] = hn.x;
                hbuf[(size_t)t*(Bb*DENC) + (b0+1)*DENC + jg] = hn.y;
                hbuf[(size_t)t*(Bb*DENC) + (b0+2)*DENC + jg] = hn.z;
                hbuf[(size_t)t*(Bb*DENC) + (b0+3)*DENC + jg] = hn.w;
            }
        }
    }
    __syncthreads();

    int bth = (tid >> 4) << 2;
    int nth = (tid & 15) << 2;
    unsigned long long accp[2][4];
#pragma unroll
    for (int p=0;p<2;p++)
#pragma unroll
        for (int j=0;j<4;j++) accp[p][j] = 0ull;

    for (int kc = 0; kc < 128; kc += 32){
#pragma unroll
        for (int q=0;q<4;q++){
            int f4 = tid*4 + q;
            int nn = f4 >> 3, kq = (f4 & 7) << 2;
            float4 v = *(const float4*)(W + (nblk*64+nn)*DENC + kbase + kc + kq);
            Ws[kq+0][nn]=v.x; Ws[kq+1][nn]=v.y; Ws[kq+2][nn]=v.z; Ws[kq+3][nn]=v.w;
        }
        __syncthreads();
#pragma unroll
        for (int kk=0; kk<32; kk++){
            F4U a4; a4.f = *(const float4*)&hsm[kc+kk][bth];
            float4 w4 = *(const float4*)&Ws[kk][nth];
            unsigned long long wd0 = dup2(w4.x);
            unsigned long long wd1 = dup2(w4.y);
            unsigned long long wd2 = dup2(w4.z);
            unsigned long long wd3 = dup2(w4.w);
            fma2(accp[0][0], a4.u[0], wd0);
            fma2(accp[0][1], a4.u[0], wd1);
            fma2(accp[0][2], a4.u[0], wd2);
            fma2(accp[0][3], a4.u[0], wd3);
            fma2(accp[1][0], a4.u[1], wd0);
            fma2(accp[1][1], a4.u[1], wd1);
            fma2(accp[1][2], a4.u[1], wd2);
            fma2(accp[1][3], a4.u[1], wd3);
        }
        __syncthreads();
    }
    float* partw = d_encpart + (t&1)*EHALF + (dir*EKS + ks)*ESLOT;
#pragma unroll
    for (int p=0;p<2;p++)
#pragma unroll
        for (int j=0;j<4;j++){
            U64F2 u; u.u = accp[p][j];
            *(float2*)(partw + (nblk*64 + nth + j)*32 + bth + 2*p) = u.f;
        }
}

// ---------------- final encoder cell: h(Ss), c(Ss) ----------------
__global__ void enc_fin(){
    int idx = blockIdx.x*256 + threadIdx.x;       // 2*8192
    int dir = idx >> 13, r = idx & 8191;
    int j = r >> 5, b = r & 31;
    const float* XGt = dir ? d_XGb : d_XGf;
    float* cbuf = dir ? d_cb : d_cf;
    float* hbuf = dir ? d_hb : d_hf;
    const float* partr = d_encpart + ((Ss-1)&1)*EHALF + dir*EKS*ESLOT;
    float g[4];
#pragma unroll
    for (int gt=0; gt<4; gt++){
        float v = XGt[((size_t)(Ss-1)*(4*DENC) + gt*DENC + j)*32 + b];
#pragma unroll
        for (int k2=0;k2<EKS;k2++) v += partr[k2*ESLOT + (gt*DENC + j)*32 + b];
        g[gt] = v;
    }
    float co = cbuf[((Ss-1)&1)*(Bb*DENC) + j*32 + b];
    float cn, hn;
    CELL1(g[0], g[1], g[2], g[3], co, cn, hn);
    cbuf[(Ss&1)*(Bb*DENC) + j*32 + b] = cn;
    hbuf[(size_t)Ss*(Bb*DENC) + b*DENC + j] = hn;
}

// ---------------- fused decoder step ----------------
// grid (32 nblk, DKS), 128 thr.
__global__ void __launch_bounds__(128) dec_fused(const float* __restrict__ Whh_d, int t)
{
    __shared__ float hsm[128][36];
    __shared__ float Ws[32][68];
    int tid = threadIdx.x;
    int nblk = blockIdx.x, ks = blockIdx.y;
    int kbase = ks*128;

    if (t == 0){
#pragma unroll
        for (int q = 0; q < 8; q++){
            int i = tid + q*128;
            int b = i >> 5, j4 = i & 31;
            float4 v = *(const float4*)(d_H + b*DDEC + kbase + j4*4);
            hsm[j4*4+0][b]=v.x; hsm[j4*4+1][b]=v.y; hsm[j4*4+2][b]=v.z; hsm[j4*4+3][b]=v.w;
        }
    } else {
        const float* partr = d_decpart + ((t-1)&1)*DHALF;
        int b0 = (tid & 7)*4, jr0 = (tid >> 3)*8;
#pragma unroll
        for (int jj = 0; jj < 8; jj++){
            int j = jr0 + jj, jg = kbase + j;
            float4 gs[4];
#pragma unroll
            for (int gt = 0; gt < 4; gt++){
                float4 v = *(const float4*)(d_XGd + ((size_t)(t-1)*(4*DDEC) + gt*DDEC + jg)*32 + b0);
#pragma unroll
                for (int k2 = 0; k2 < DKS; k2++){
                    float4 p = *(const float4*)(partr + k2*DSLOT + (gt*DDEC + jg)*32 + b0);
                    v.x += p.x; v.y += p.y; v.z += p.z; v.w += p.w;
                }
                gs[gt] = v;
            }
            float4 co = *(const float4*)(d_cd + ((t-1)&1)*(Bb*DDEC) + jg*32 + b0);
            float4 cn, hn;
            CELL1(gs[0].x, gs[1].x, gs[2].x, gs[3].x, co.x, cn.x, hn.x);
            CELL1(gs[0].y, gs[1].y, gs[2].y, gs[3].y, co.y, cn.y, hn.y);
            CELL1(gs[0].z, gs[1].z, gs[2].z, gs[3].z, co.z, cn.z, hn.z);
            CELL1(gs[0].w, gs[1].w, gs[2].w, gs[3].w, co.w, cn.w, hn.w);
            *(float4*)(d_cd + (t&1)*(Bb*DDEC) + jg*32 + b0) = cn;
            *(float4*)&hsm[j][b0] = hn;
            if (nblk == 0){
                d_H[(size_t)t*(Bb*DDEC) + (b0+0)*DDEC + jg] = hn.x;
                d_H[(size_t)t*(Bb*DDEC) + (b0+1)*DDEC + jg] = hn.y;
                d_H[(size_t)t*(Bb*DDEC) + (b0+2)*DDEC + jg] = hn.z;
                d_H[(size_t)t*(Bb*DDEC) + (b0+3)*DDEC + jg] = hn.w;
            }
        }
    }
    __syncthreads();

    int bth = (tid >> 4) << 2;
    int nth = (tid & 15) << 2;
    unsigned long long accp[2][4];
#pragma unroll
    for (int p=0;p<2;p++)
#pragma unroll
        for (int j=0;j<4;j++) accp[p][j] = 0ull;

    for (int kc = 0; kc < 128; kc += 32){
#pragma unroll
        for (int q=0;q<4;q++){
            int f4 = tid*4 + q;
            int nn = f4 >> 3, kq = (f4 & 7) << 2;
            float4 v = *(const float4*)(Whh_d + (size_t)(nblk*64+nn)*DDEC + kbase + kc + kq);
            Ws[kq+0][nn]=v.x; Ws[kq+1][nn]=v.y; Ws[kq+2][nn]=v.z; Ws[kq+3][nn]=v.w;
        }
        __syncthreads();
#pragma unroll
        for (int kk=0; kk<32; kk++){
            F4U a4; a4.f = *(const float4*)&hsm[kc+kk][bth];
            float4 w4 = *(const float4*)&Ws[kk][nth];
            unsigned long long wd0 = dup2(w4.x);
            unsigned long long wd1 = dup2(w4.y);
            unsigned long long wd2 = dup2(w4.z);
            unsigned long long wd3 = dup2(w4.w);
            fma2(accp[0][0], a4.u[0], wd0);
            fma2(accp[0][1], a4.u[0], wd1);
            fma2(accp[0][2], a4.u[0], wd2);
            fma2(accp[0][3], a4.u[0], wd3);
            fma2(accp[1][0], a4.u[1], wd0);
            fma2(accp[1][1], a4.u[1], wd1);
            fma2(accp[1][2], a4.u[1], wd2);
            fma2(accp[1][3], a4.u[1], wd3);
        }
        __syncthreads();
    }
    float* partw = d_decpart + (t&1)*DHALF + ks*DSLOT;
#pragma unroll
    for (int p=0;p<2;p++)
#pragma unroll
        for (int j=0;j<4;j++){
            U64F2 u; u.u = accp[p][j];
            *(float2*)(partw + (nblk*64 + nth + j)*32 + bth + 2*p) = u.f;
        }
}

// ---------------- final decoder cell: h(Tt) ----------------
__global__ void dec_fin(){
    int idx = blockIdx.x*256 + threadIdx.x;       // 16384
    int j = idx >> 5, b = idx & 31;
    const float* partr = d_decpart + ((Tt-1)&1)*DHALF;
    float g[4];
#pragma unroll
    for (int gt=0; gt<4; gt++){
        float v = d_XGd[((size_t)(Tt-1)*(4*DDEC) + gt*DDEC + j)*32 + b];
#pragma unroll
        for (int k2=0;k2<DKS;k2++) v += partr[k2*DSLOT + (gt*DDEC + j)*32 + b];
        g[gt] = v;
    }
    float co = d_cd[((Tt-1)&1)*(Bb*DDEC) + j*32 + b];
    float cn, hn;
    CELL1(g[0], g[1], g[2], g[3], co, cn, hn);
    d_cd[(Tt&1)*(Bb*DDEC) + j*32 + b] = cn;
    d_H[(size_t)Tt*(Bb*DDEC) + b*DDEC + j] = hn;
}

// ---------------- small-M GEMM (ct path only; old [b][N] partial layout) ----------
__global__ void __launch_bounds__(128) lstm_hgemm(
    const float* __restrict__ H0, const float* __restrict__ W0,
    float* __restrict__ part, int Ntot, int KH, int KS)
{
    int n0blk = blockIdx.x * 64;
    int ksub = KH / KS;
    int kbase = blockIdx.y * ksub;
    __shared__ float As[32][36];
    __shared__ float Ws[32][68];
    int tid = threadIdx.x;
    int bth = (tid >> 4) << 2;
    int nth = (tid & 15) << 2;
    float acc[4][4];
#pragma unroll
    for (int i=0;i<4;i++)
#pragma unroll
        for (int j=0;j<4;j++) acc[i][j] = 0.f;

    for (int k0 = 0; k0 < ksub; k0 += 32){
#pragma unroll
        for (int q=0;q<2;q++){
            int f4 = tid*2 + q;
            int bb = f4 >> 3, kq = (f4 & 7) << 2;
            float4 v = *(const float4*)(H0 + bb*KH + kbase + k0 + kq);
            As[kq+0][bb]=v.x; As[kq+1][bb]=v.y; As[kq+2][bb]=v.z; As[kq+3][bb]=v.w;
        }
#pragma unroll
        for (int q=0;q<4;q++){
            int f4 = tid*4 + q;
            int nn = f4 >> 3, kq = (f4 & 7) << 2;
            float4 v = *(const float4*)(W0 + (n0blk+nn)*KH + kbase + k0 + kq);
            Ws[kq+0][nn]=v.x; Ws[kq+1][nn]=v.y; Ws[kq+2][nn]=v.z; Ws[kq+3][nn]=v.w;
        }
        __syncthreads();
#pragma unroll
        for (int kk=0; kk<32; kk++){
            float4 a4 = *(const float4*)&As[kk][bth];
            float4 w4 = *(const float4*)&Ws[kk][nth];
            float aa[4] = {a4.x,a4.y,a4.z,a4.w};
            float ww[4] = {w4.x,w4.y,w4.z,w4.w};
#pragma unroll
            for (int i=0;i<4;i++)
#pragma unroll
                for (int j=0;j<4;j++) acc[i][j] += aa[i]*ww[j];
        }
        __syncthreads();
    }
    float* pbase = part + (blockIdx.y*32)*Ntot;
#pragma unroll
    for (int i=0;i<4;i++){
        float4 v; v.x=acc[i][0]; v.y=acc[i][1]; v.z=acc[i][2]; v.w=acc[i][3];
        *(float4*)&pbase[(bth+i)*Ntot + n0blk + nth] = v;
    }
}

// ---------------- misc glue ----------------
__global__ void mem_assemble(){
    int idx = blockIdx.x*256 + threadIdx.x;
    int b = idx >> 16, r = idx & 65535;
    int s = r >> 9, d = r & 511;
    float v;
    if (d < DENC) v = d_hf[((s+1)*Bb + b)*DENC + d];
    else          v = d_hb[((Ss - s)*Bb + b)*DENC + (d - DENC)];
    d_mem[idx] = v;
}
__global__ void ccat_build(){
    int idx = blockIdx.x*256 + threadIdx.x;
    int b = idx >> 9, j = idx & 511;
    // c(Ss) lives in buffer 0 (Ss even), j-major layout
    d_ccat[idx] = (j < DENC) ? d_cf[j*32 + b] : d_cb[(j - DENC)*32 + b];
}
__global__ void ct_combine(){
    int idx = blockIdx.x*256 + threadIdx.x;
    int b = idx >> 9, j = idx & 511;
    float v = 0.f;
#pragma unroll
    for (int ky=0; ky<4; ky++) v += d_decpart[(ky*Bb + b)*DDEC + j];
    d_cd[j*32 + b] = lrelu_f(v);        // buffer 0, j-major
}

// ---------------- attention ----------------
__global__ void __launch_bounds__(256) attn_kernel(){
    int b  = blockIdx.x;
    int t0 = blockIdx.y * 8;
    __shared__ float hs[8][512];
    __shared__ float sc[8][128];
    int tid = threadIdx.x;
    for (int i = tid; i < 8*512; i += 256){
        int tt = i >> 9, d = i & 511;
        hs[tt][d] = d_H[((t0 + tt + 1)*Bb + b)*DDEC + d];
    }
    __syncthreads();
    int w = tid >> 5, lane = tid & 31;
    const float scale = 0.04419417382415922f;
    for (int si = 0; si < 16; si++){
        int s = w*16 + si;
        const float* mrow = d_mem + (b*Ss + s)*DDEC;
        float acc[8] = {0,0,0,0,0,0,0,0};
#pragma unroll
        for (int q=0; q<4; q++){
            int d = q*128 + lane*4;
            float4 m4 = *(const float4*)(mrow + d);
#pragma unroll
            for (int tt=0; tt<8; tt++){
                float4 h4 = *(const float4*)&hs[tt][d];
                acc[tt] += m4.x*h4.x + m4.y*h4.y + m4.z*h4.z + m4.w*h4.w;
            }
        }
#pragma unroll
        for (int tt=0; tt<8; tt++){
            float v = acc[tt];
#pragma unroll
            for (int o=16;o>0;o>>=1) v += __shfl_xor_sync(0xffffffffu, v, o);
            if (lane == 0) sc[tt][s] = v * scale;
        }
    }
    __syncthreads();
    {
        int tt = w;
        float vals[4], m = -1e30f;
#pragma unroll
        for (int q=0;q<4;q++){ vals[q] = sc[tt][lane + q*32]; m = fmaxf(m, vals[q]); }
#pragma unroll
        for (int o=16;o>0;o>>=1) m = fmaxf(m, __shfl_xor_sync(0xffffffffu, m, o));
        float ssum = 0.f;
#pragma unroll
        for (int q=0;q<4;q++){ vals[q] = __expf(vals[q]-m); ssum += vals[q]; }
#pragma unroll
        for (int o=16;o>0;o>>=1) ssum += __shfl_xor_sync(0xffffffffu, ssum, o);
        float inv = 1.f/ssum;
#pragma unroll
        for (int q=0;q<4;q++) sc[tt][lane + q*32] = vals[q]*inv;
    }
    __syncthreads();
    {
        int d0 = tid*2;
        float acc[8][2];
#pragma unroll
        for (int tt=0;tt<8;tt++){ acc[tt][0]=0.f; acc[tt][1]=0.f; }
        for (int s=0; s<Ss; s++){
            float2 m2 = *(const float2*)(d_mem + (b*Ss + s)*DDEC + d0);
#pragma unroll
            for (int tt=0;tt<8;tt++){
                float p = sc[tt][s];
                acc[tt][0] += p*m2.x; acc[tt][1] += p*m2.y;
            }
        }
#pragma unroll
        for (int tt=0;tt<8;tt++){
            int rr = (t0+tt)*Bb + b;
            float2 v; v.x = acc[tt][0]; v.y = acc[tt][1];
            *(float2*)&d_FFN[rr*(2*DDEC) + DDEC + d0] = v;
        }
    }
    for (int i = tid; i < 8*512; i += 256){
        int tt = i >> 9, d = i & 511;
        int rr = (t0+tt)*Bb + b;
        d_FFN[rr*(2*DDEC) + d] = hs[tt][d];
    }
}

// ---------------- launcher ----------------
extern "C" void kernel_launch(void* const* d_in, const int* in_sizes, int n_in,
                              void* d_out, int out_size)
{
    const int*   inp        = (const int*)  d_in[0];
    const int*   label_i    = (const int*)  d_in[1];
    const int*   x          = (const int*)  d_in[2];
    const int*   label      = (const int*)  d_in[3];
    const float* start_emb  = (const float*)d_in[4];
    const float* tok_emb    = (const float*)d_in[5];
    const float* enc_style  = (const float*)d_in[6];
    const float* style_emb  = (const float*)d_in[7];
    const float* Wih_f      = (const float*)d_in[8];
    const float* Whh_f      = (const float*)d_in[9];
    const float* bih_f      = (const float*)d_in[10];
    const float* bhh_f      = (const float*)d_in[11];
    const float* Wih_b      = (const float*)d_in[12];
    const float* Whh_b      = (const float*)d_in[13];
    const float* bih_b      = (const float*)d_in[14];
    const float* bhh_b      = (const float*)d_in[15];
    const float* Wih_d      = (const float*)d_in[16];
    const float* Whh_d      = (const float*)d_in[17];
    const float* bih_d      = (const float*)d_in[18];
    const float* bhh_d      = (const float*)d_in[19];
    const float* W_tr       = (const float*)d_in[20];
    const float* W_f1       = (const float*)d_in[21];
    const float* b_f1       = (const float*)d_in[22];
    const float* W_f2       = (const float*)d_in[23];
    float* out = (float*)d_out;

    float *embS, *decin, *XGf, *XGb, *XGd, *ccat, *decpart, *FFN, *HID;
    __half *Wf16, *HIDH;
    cudaGetSymbolAddress((void**)&embS,   d_embS);
    cudaGetSymbolAddress((void**)&decin,  d_decin);
    cudaGetSymbolAddress((void**)&XGf,    d_XGf);
    cudaGetSymbolAddress((void**)&XGb,    d_XGb);
    cudaGetSymbolAddress((void**)&XGd,    d_XGd);
    cudaGetSymbolAddress((void**)&ccat,   d_ccat);
    cudaGetSymbolAddress((void**)&decpart,d_decpart);
    cudaGetSymbolAddress((void**)&FFN,    d_FFN);
    cudaGetSymbolAddress((void**)&HID,    d_HID);
    cudaGetSymbolAddress((void**)&Wf16,   d_Wf16);
    cudaGetSymbolAddress((void**)&HIDH,   d_HIDH);

    cudaFuncSetAttribute(f2_mma, cudaFuncAttributeMaxDynamicSharedMemorySize, F2_SMEM);

    // prep
    p_emb  <<<2048,256>>>(inp, tok_emb);
    p_decin<<<2048,256>>>(x, tok_emb, start_emb);
    p_init <<<192,256>>>(label_i, label, enc_style, style_emb);
    conv_w16<<<64000,256>>>(W_f2, Wf16, Vv*DDEC);

    // batched x-part of LSTM gates, stored TRANSPOSED [t][n][b] (biases folded)
    gemm_nt<<<dim3( 8,32),256>>>(embS,  Wih_f, XGf, 4096,1024, 128, bih_f, bhh_f, 0,0,1);
    gemm_nt<<<dim3( 8,32),256>>>(embS,  Wih_b, XGb, 4096,1024, 128, bih_b, bhh_b, 0,1,1);
    gemm_nt<<<dim3(16,32),256>>>(decin, Wih_d, XGd, 4096,2048, 128, bih_d, bhh_d, 0,0,1);

    // encoder recurrence: ONE fused node per step
    for (int t = 0; t < Ss; t++)
        enc_fused<<<dim3(16,EKS,2),128>>>(Whh_f, Whh_b, t);
    enc_fin<<<64,256>>>();
    mem_assemble<<<8192,256>>>();

    // c_t = lrelu(concat(cf,cb) @ W_tr^T)
    ccat_build<<<64,256>>>();
    lstm_hgemm<<<dim3(8,4),128>>>(ccat, W_tr, decpart, DDEC, DDEC, 4);
    ct_combine<<<64,256>>>();

    // decoder recurrence: ONE fused node per step
    for (int t = 0; t < Tt; t++)
        dec_fused<<<dim3(32,DKS),128>>>(Whh_d, t);
    dec_fin<<<64,256>>>();

    // batched attention -> FFN input
    attn_kernel<<<dim3(32,16),256>>>();

    // F1: lrelu(FFN @ W_f1^T + b_f1)
    gemm_nt<<<dim3(4,32),256>>>(FFN, W_f1, HID, 4096, 512, 1024, b_f1, nullptr, 1,0,0);
    conv_w16<<<8192,256>>>(HID, HIDH, Tt*Bb*DDEC);

    // F2 on tensor cores: single-pass fp16, remapped to [B,T,V]
    f2_mma<<<dim3(32,125), 256, F2_SMEM>>>(HIDH, Wf16, out);
}

// round 16
// speedup vs baseline: 1.5954x; 1.5954x over previous
#include <cuda_runtime.h>
#include <cuda_bf16.h>
#include <cuda_fp16.h>
#include <cstdint>

#define Bb 32
#define Ss 128
#define Tt 128
#define DEMB 128
#define DENC 256
#define DDEC 512
#define Vv 32000

// ---------------- scratch (device globals; no runtime allocation) ----------------
__device__ float d_embS [Ss*Bb*DEMB];
__device__ float d_decin[Tt*Bb*DEMB];
__device__ float d_XGf  [Ss*Bb*4*DENC];
__device__ float d_XGb  [Ss*Bb*4*DENC];
__device__ float d_XGd  [Tt*Bb*4*DDEC];
__device__ float d_hf   [(Ss+1)*Bb*DENC];
__device__ float d_hb   [(Ss+1)*Bb*DENC];
__device__ float d_cf   [2*Bb*DENC];
__device__ float d_cb   [2*Bb*DENC];
__device__ float d_encpart[2*4*Bb*4*DENC];     // [dir][ks(4)][b][1024]
__device__ float d_mem  [Bb*Ss*2*DENC];
__device__ float d_ccat [Bb*2*DENC];
__device__ float d_H    [(Tt+1)*Bb*DDEC];
__device__ float d_cd   [2*Bb*DDEC];
__device__ float d_decpart[8*Bb*4*DDEC];       // [ks(8)][b][2048]; also reused by ct path
__device__ float d_FFN  [Tt*Bb*2*DDEC];
__device__ float d_HID  [Tt*Bb*DDEC];
// fp16 operands for tensor-core F2
__device__ __half d_Wf16 [Vv*DDEC];
__device__ __half d_HIDH [Tt*Bb*DDEC];

// ---------------- helpers ----------------
__device__ __forceinline__ float lrelu_f(float x){ return x >= 0.f ? x : 0.1f*x; }
__device__ __forceinline__ float sigm_f (float x){ return 1.f/(1.f+__expf(-x)); }
__device__ __forceinline__ float tanh_f (float x){
    float ax = fabsf(x);
    float e  = __expf(-2.f*ax);
    float r  = (1.f-e)/(1.f+e);
    return x >= 0.f ? r : -r;
}
__device__ __forceinline__ unsigned long long dup2(float a){
    unsigned long long r;
    asm("mov.b64 %0, {%1, %1};" : "=l"(r) : "f"(a));
    return r;
}
__device__ __forceinline__ void fma2(unsigned long long &c, unsigned long long a, unsigned long long w){
    asm("fma.rn.f32x2 %0, %1, %2, %0;" : "+l"(c) : "l"(a), "l"(w));
}
union F4U { float4 f; unsigned long long u[2]; };
union U64F2 { unsigned long long u; float2 f; };

__device__ __forceinline__ void pdl_trigger(){
    asm volatile("griddepcontrol.launch_dependents;" ::: "memory");
}
__device__ __forceinline__ void pdl_wait(){
    asm volatile("griddepcontrol.wait;" ::: "memory");
}

__device__ __forceinline__ uint32_t smem_u32(const void* p){
    uint32_t a; asm("{ .reg .u64 t; cvta.to.shared.u64 t, %1; cvt.u32.u64 %0, t; }" : "=r"(a) : "l"(p));
    return a;
}
__device__ __forceinline__ void cp16(uint32_t saddr, const void* gaddr){
    asm volatile("cp.async.cg.shared.global [%0], [%1], 16;" :: "r"(saddr), "l"(gaddr));
}
__device__ __forceinline__ void ldm_x4(uint32_t addr, uint32_t &r0, uint32_t &r1, uint32_t &r2, uint32_t &r3){
    asm volatile("ldmatrix.sync.aligned.m8n8.x4.shared.b16 {%0,%1,%2,%3}, [%4];"
                 : "=r"(r0), "=r"(r1), "=r"(r2), "=r"(r3) : "r"(addr));
}
__device__ __forceinline__ void mma16816h(float* c, uint32_t a0, uint32_t a1, uint32_t a2, uint32_t a3,
                                          uint32_t b0, uint32_t b1){
    asm volatile("mma.sync.aligned.m16n8k16.row.col.f32.f16.f16.f32 "
                 "{%0,%1,%2,%3}, {%4,%5,%6,%7}, {%8,%9}, {%0,%1,%2,%3};"
                 : "+f"(c[0]), "+f"(c[1]), "+f"(c[2]), "+f"(c[3])
                 : "r"(a0), "r"(a1), "r"(a2), "r"(a3), "r"(b0), "r"(b1));
}

// ---------------- prep kernels ----------------
__global__ void p_emb(const int* __restrict__ inp, const float* __restrict__ tok_emb){
    int idx = blockIdx.x*256 + threadIdx.x;
    int sb = idx >> 7, d = idx & 127;
    int s = sb >> 5, b = sb & 31;
    d_embS[idx] = tok_emb[inp[b*Ss + s]*DEMB + d];
}
__global__ void p_decin(const int* __restrict__ x, const float* __restrict__ tok_emb,
                        const float* __restrict__ start_emb){
    int idx = blockIdx.x*256 + threadIdx.x;
    int tb = idx >> 7, d = idx & 127;
    int t = tb >> 5, b = tb & 31;
    d_decin[idx] = (t == 0) ? start_emb[d] : tok_emb[x[b*Tt + (t-1)]*DEMB + d];
}
__global__ void p_init(const int* __restrict__ label_i, const int* __restrict__ label,
                       const float* __restrict__ enc_style_emb, const float* __restrict__ style_emb){
    int idx = blockIdx.x*256 + threadIdx.x;
    if (idx < 16384){
        int dir = idx >> 13, r = idx & 8191;
        int b = r >> 8, j = r & 255;
        float v = enc_style_emb[label_i[b]*(2*DENC) + dir*DENC + j];
        (dir ? d_hb : d_hf)[b*DENC + j] = v;
    } else if (idx < 32768){
        int r = idx - 16384;
        int dir = r >> 13; r &= 8191;
        (dir ? d_cb : d_cf)[r] = 0.f;
    } else {
        int r = idx - 32768;
        int b = r >> 9, j = r & 511;
        d_H[b*DDEC + j] = style_emb[label[b]*DDEC + j];
    }
}
__global__ void conv_w16(const float* __restrict__ src, __half* __restrict__ dst, int n){
    int i = blockIdx.x*256 + threadIdx.x;
    if (i < n) dst[i] = __float2half_rn(src[i]);
}

// ---------------- fp32 GEMM (XG / F1): C = A @ W^T ----------------
__global__ void __launch_bounds__(256) gemm_nt(
    const float* __restrict__ A, const float* __restrict__ W, float* __restrict__ C,
    int M, int N, int K,
    const float* __restrict__ bias1, const float* __restrict__ bias2,
    int act, int remapA)
{
    __shared__ float As[8][128];
    __shared__ float Bs[8][128];
    int tid = threadIdx.x;
    int bm = blockIdx.y * 128, bn = blockIdx.x * 128;
    int lr = tid >> 1;
    int lc = (tid & 1) << 2;
    int arow = bm + lr;
    if (remapA) arow = ((Ss-1 - (arow >> 5)) << 5) | (arow & 31);
    const float* Aptr = A + arow*K + lc;
    const float* Wptr = W + (bn + lr)*K + lc;

    int m0 = (tid >> 4) << 3;
    int n0 = (tid & 15) << 3;
    unsigned long long acc[8][4];
#pragma unroll
    for (int i=0;i<8;i++)
#pragma unroll
        for (int j=0;j<4;j++) acc[i][j] = 0ull;

    for (int k0 = 0; k0 < K; k0 += 8){
        float4 a4 = *(const float4*)(Aptr + k0);
        float4 w4 = *(const float4*)(Wptr + k0);
        As[lc+0][lr]=a4.x; As[lc+1][lr]=a4.y; As[lc+2][lr]=a4.z; As[lc+3][lr]=a4.w;
        Bs[lc+0][lr]=w4.x; Bs[lc+1][lr]=w4.y; Bs[lc+2][lr]=w4.z; Bs[lc+3][lr]=w4.w;
        __syncthreads();
#pragma unroll
        for (int kk=0; kk<8; kk++){
            float4 a0 = *(const float4*)&As[kk][m0];
            float4 a1 = *(const float4*)&As[kk][m0+4];
            F4U ub0, ub1;
            ub0.f = *(const float4*)&Bs[kk][n0];
            ub1.f = *(const float4*)&Bs[kk][n0+4];
            unsigned long long w0=ub0.u[0], w1=ub0.u[1], w2=ub1.u[0], w3=ub1.u[1];
            float av[8] = {a0.x,a0.y,a0.z,a0.w,a1.x,a1.y,a1.z,a1.w};
#pragma unroll
            for (int i=0;i<8;i++){
                unsigned long long ad = dup2(av[i]);
                fma2(acc[i][0], ad, w0);
                fma2(acc[i][1], ad, w1);
                fma2(acc[i][2], ad, w2);
                fma2(acc[i][3], ad, w3);
            }
        }
        __syncthreads();
    }
#pragma unroll
    for (int i=0;i<8;i++){
        int mg = bm + m0 + i;
#pragma unroll
        for (int j=0;j<4;j++){
            U64F2 u; u.u = acc[i][j];
            float2 v = u.f;
            int ng = bn + n0 + 2*j;
            if (bias1){ v.x += bias1[ng]; v.y += bias1[ng+1]; }
            if (bias2){ v.x += bias2[ng]; v.y += bias2[ng+1]; }
            if (act){ v.x = lrelu_f(v.x); v.y = lrelu_f(v.y); }
            *(float2*)&C[mg*N + ng] = v;
        }
    }
}

// ---------------- mma.sync fp16 single-pass F2 GEMM ----------------
#define F2_NCHUNK 16
#define F2_ASTG   (128*40*2)
#define F2_BSTG   (256*40*2)
#define F2_STG    (F2_ASTG + F2_BSTG)
#define F2_SMEM   (3*F2_STG)
__global__ void __launch_bounds__(256) f2_mma(
    const __half* __restrict__ AH, const __half* __restrict__ Bg, float* __restrict__ out)
{
    extern __shared__ __half sm[];
    int tid = threadIdx.x;
    int wid = tid >> 5, lane = tid & 31;
    int warp_m = wid & 1, warp_n = wid >> 1;
    int bm = blockIdx.x * 128;
    int bn = blockIdx.y * 256;
    uint32_t sbase = smem_u32(sm);

    float acc[4][8][4];
#pragma unroll
    for (int i=0;i<4;i++)
#pragma unroll
        for (int j=0;j<8;j++)
#pragma unroll
            for (int q=0;q<4;q++) acc[i][j][q] = 0.f;

    auto load_chunk = [&](int c, int s){
        int k0 = c * 32;
        uint32_t base = sbase + (uint32_t)s * F2_STG;
#pragma unroll
        for (int q=0; q<2; q++){
            int i = q*256 + tid;
            int row = i >> 2, sg = i & 3;
            cp16(base + (uint32_t)(row*80 + sg*16), AH + (size_t)(bm + row)*DDEC + k0 + sg*8);
        }
#pragma unroll
        for (int q=0; q<4; q++){
            int i = q*256 + tid;
            int row = i >> 2, sg = i & 3;
            cp16(base + F2_ASTG + (uint32_t)(row*80 + sg*16),
                 Bg + (size_t)(bn + row)*DDEC + k0 + sg*8);
        }
        asm volatile("cp.async.commit_group;" ::: "memory");
    };

    load_chunk(0, 0);
    load_chunk(1, 1);

    int ld_s = 2, cs = 0;
    for (int c = 0; c < F2_NCHUNK; c++){
        if (c < F2_NCHUNK-1) asm volatile("cp.async.wait_group 1;" ::: "memory");
        else                 asm volatile("cp.async.wait_group 0;" ::: "memory");
        __syncthreads();
        if (c + 2 < F2_NCHUNK){
            load_chunk(c+2, ld_s);
            ld_s++; if (ld_s == 3) ld_s = 0;
        }
        uint32_t baseA = sbase + (uint32_t)cs * F2_STG;
        uint32_t baseB = baseA + F2_ASTG;
#pragma unroll
        for (int ks = 0; ks < 2; ks++){
            int kc = ks * 16;
            int g = lane >> 3, r = lane & 7;
            uint32_t af[4][4];
#pragma unroll
            for (int mt=0; mt<4; mt++){
                int row = warp_m*64 + mt*16 + (g & 1)*8 + r;
                int col = kc + (g >> 1)*8;
                ldm_x4(baseA + (uint32_t)(row*80 + col*2), af[mt][0], af[mt][1], af[mt][2], af[mt][3]);
            }
            uint32_t bf[8][2];
#pragma unroll
            for (int j=0; j<4; j++){
                int nrow = warp_n*64 + (j*2 + (g >> 1))*8 + r;
                int col = kc + (g & 1)*8;
                ldm_x4(baseB + (uint32_t)(nrow*80 + col*2),
                       bf[j*2][0], bf[j*2][1], bf[j*2+1][0], bf[j*2+1][1]);
            }
#pragma unroll
            for (int mt=0; mt<4; mt++)
#pragma unroll
                for (int nt=0; nt<8; nt++)
                    mma16816h(acc[mt][nt], af[mt][0], af[mt][1], af[mt][2], af[mt][3],
                              bf[nt][0], bf[nt][1]);
        }
        __syncthreads();
        cs++; if (cs == 3) cs = 0;
    }

#pragma unroll
    for (int mt=0; mt<4; mt++){
#pragma unroll
        for (int half=0; half<2; half++){
            int mg = bm + warp_m*64 + mt*16 + (lane >> 2) + half*8;
            int t = mg >> 5, b = mg & 31;
            float* dst = out + (size_t)(b*Tt + t)*Vv + bn + warp_n*64;
#pragma unroll
            for (int nt=0; nt<8; nt++){
                float2 v;
                v.x = acc[mt][nt][half*2+0];
                v.y = acc[mt][nt][half*2+1];
                *(float2*)&dst[nt*8 + 2*(lane & 3)] = v;
            }
        }
    }
}

// ---------------- small-M recurrence GEMM (f32x2-packed, PDL) ----------------
__global__ void __launch_bounds__(128) lstm_hgemm(
    const float* __restrict__ H0, const float* __restrict__ H1,
    const float* __restrict__ W0, const float* __restrict__ W1,
    float* __restrict__ part, int Ntot, int KH, int KS)
{
    pdl_trigger();                      // let successor pre-launch
    int dir = blockIdx.z;
    const float* Hd = dir ? H1 : H0;
    const float* Wd = dir ? W1 : W0;
    int n0blk = blockIdx.x * 64;
    int ksub = KH / KS;
    int kbase = blockIdx.y * ksub;
    __shared__ float As[32][36];
    __shared__ float Ws[32][68];
    int tid = threadIdx.x;
    int bth = (tid >> 4) << 2;
    int nth = (tid & 15) << 2;
    unsigned long long accp[2][4];
#pragma unroll
    for (int p=0;p<2;p++)
#pragma unroll
        for (int j=0;j<4;j++) accp[p][j] = 0ull;

    pdl_wait();                         // predecessor writes (h) now visible

    for (int k0 = 0; k0 < ksub; k0 += 32){
#pragma unroll
        for (int q=0;q<2;q++){
            int f4 = tid*2 + q;
            int bb = f4 >> 3, kq = (f4 & 7) << 2;
            float4 v = *(const float4*)(Hd + bb*KH + kbase + k0 + kq);
            As[kq+0][bb]=v.x; As[kq+1][bb]=v.y; As[kq+2][bb]=v.z; As[kq+3][bb]=v.w;
        }
#pragma unroll
        for (int q=0;q<4;q++){
            int f4 = tid*4 + q;
            int nn = f4 >> 3, kq = (f4 & 7) << 2;
            float4 v = *(const float4*)(Wd + (n0blk+nn)*KH + kbase + k0 + kq);
            Ws[kq+0][nn]=v.x; Ws[kq+1][nn]=v.y; Ws[kq+2][nn]=v.z; Ws[kq+3][nn]=v.w;
        }
        __syncthreads();
#pragma unroll
        for (int kk=0; kk<32; kk++){
            F4U a4; a4.f = *(const float4*)&As[kk][bth];
            float4 w4 = *(const float4*)&Ws[kk][nth];
            unsigned long long wd0 = dup2(w4.x);
            unsigned long long wd1 = dup2(w4.y);
            unsigned long long wd2 = dup2(w4.z);
            unsigned long long wd3 = dup2(w4.w);
            fma2(accp[0][0], a4.u[0], wd0);
            fma2(accp[0][1], a4.u[0], wd1);
            fma2(accp[0][2], a4.u[0], wd2);
            fma2(accp[0][3], a4.u[0], wd3);
            fma2(accp[1][0], a4.u[1], wd0);
            fma2(accp[1][1], a4.u[1], wd1);
            fma2(accp[1][2], a4.u[1], wd2);
            fma2(accp[1][3], a4.u[1], wd3);
        }
        __syncthreads();
    }
    float* pbase = part + ((dir*KS + blockIdx.y)*32)*Ntot;
#pragma unroll
    for (int p=0;p<2;p++){
        U64F2 c0,c1,c2,c3;
        c0.u=accp[p][0]; c1.u=accp[p][1]; c2.u=accp[p][2]; c3.u=accp[p][3];
        float4 vlo; vlo.x=c0.f.x; vlo.y=c1.f.x; vlo.z=c2.f.x; vlo.w=c3.f.x;
        float4 vhi; vhi.x=c0.f.y; vhi.y=c1.f.y; vhi.z=c2.f.y; vhi.w=c3.f.y;
        *(float4*)&pbase[(bth+2*p+0)*Ntot + n0blk + nth] = vlo;
        *(float4*)&pbase[(bth+2*p+1)*Ntot + n0blk + nth] = vhi;
    }
}

// ---------------- cell updates (PDL) ----------------
__global__ void enc_cell(int t){
    pdl_trigger();
    pdl_wait();
    int idx = blockIdx.x*256 + threadIdx.x;
    int dir = idx >> 13, r = idx & 8191;
    int b = r >> 8, j = r & 255;
    const float* XG = dir ? d_XGb : d_XGf;
    float g[4];
#pragma unroll
    for (int gt=0; gt<4; gt++){
        int n = gt*DENC + j;
        float v = XG[(t*Bb + b)*(4*DENC) + n];
#pragma unroll
        for (int ks=0; ks<4; ks++)
            v += d_encpart[((dir*4+ks)*Bb + b)*(4*DENC) + n];
        g[gt] = v;
    }
    float* cbuf = dir ? d_cb : d_cf;
    float cold = cbuf[(t&1)*Bb*DENC + b*DENC + j];
    float i_ = sigm_f(g[0]), f_ = sigm_f(g[1]), gg = tanh_f(g[2]), o_ = sigm_f(g[3]);
    float cn = f_*cold + i_*gg;
    float hn = o_*tanh_f(cn);
    cbuf[((t+1)&1)*Bb*DENC + b*DENC + j] = cn;
    (dir ? d_hb : d_hf)[((t+1)*Bb + b)*DENC + j] = hn;
}
__global__ void dec_cell(int t){
    pdl_trigger();
    pdl_wait();
    int idx = blockIdx.x*256 + threadIdx.x;
    int b = idx >> 9, j = idx & 511;
    float g[4];
#pragma unroll
    for (int gt=0; gt<4; gt++){
        int n = gt*DDEC + j;
        float v = d_XGd[(t*Bb + b)*(4*DDEC) + n];
#pragma unroll
        for (int ky=0; ky<8; ky++) v += d_decpart[(ky*Bb + b)*(4*DDEC) + n];
        g[gt] = v;
    }
    float cold = d_cd[(t&1)*Bb*DDEC + b*DDEC + j];
    float i_ = sigm_f(g[0]), f_ = sigm_f(g[1]), gg = tanh_f(g[2]), o_ = sigm_f(g[3]);
    float cn = f_*cold + i_*gg;
    float hn = o_*tanh_f(cn);
    d_cd[((t+1)&1)*Bb*DDEC + b*DDEC + j] = cn;
    d_H[((t+1)*Bb + b)*DDEC + j] = hn;
}

// ---------------- misc glue ----------------
__global__ void mem_assemble(){
    int idx = blockIdx.x*256 + threadIdx.x;
    int b = idx >> 16, r = idx & 65535;
    int s = r >> 9, d = r & 511;
    float v;
    if (d < DENC) v = d_hf[((s+1)*Bb + b)*DENC + d];
    else          v = d_hb[((Ss - s)*Bb + b)*DENC + (d - DENC)];
    d_mem[idx] = v;
}
__global__ void ccat_build(){
    int idx = blockIdx.x*256 + threadIdx.x;
    int b = idx >> 9, j = idx & 511;
    d_ccat[idx] = (j < DENC) ? d_cf[b*DENC + j] : d_cb[b*DENC + (j - DENC)];
}
__global__ void ct_combine(){
    int idx = blockIdx.x*256 + threadIdx.x;
    int b = idx >> 9, j = idx & 511;
    float v = 0.f;
#pragma unroll
    for (int ky=0; ky<4; ky++) v += d_decpart[(ky*Bb + b)*DDEC + j];
    d_cd[b*DDEC + j] = lrelu_f(v);
}

// ---------------- attention ----------------
__global__ void __launch_bounds__(256) attn_kernel(){
    int b  = blockIdx.x;
    int t0 = blockIdx.y * 8;
    __shared__ float hs[8][512];
    __shared__ float sc[8][128];
    int tid = threadIdx.x;
    for (int i = tid; i < 8*512; i += 256){
        int tt = i >> 9, d = i & 511;
        hs[tt][d] = d_H[((t0 + tt + 1)*Bb + b)*DDEC + d];
    }
    __syncthreads();
    int w = tid >> 5, lane = tid & 31;
    const float scale = 0.04419417382415922f;
    for (int si = 0; si < 16; si++){
        int s = w*16 + si;
        const float* mrow = d_mem + (b*Ss + s)*DDEC;
        float acc[8] = {0,0,0,0,0,0,0,0};
#pragma unroll
        for (int q=0; q<4; q++){
            int d = q*128 + lane*4;
            float4 m4 = *(const float4*)(mrow + d);
#pragma unroll
            for (int tt=0; tt<8; tt++){
                float4 h4 = *(const float4*)&hs[tt][d];
                acc[tt] += m4.x*h4.x + m4.y*h4.y + m4.z*h4.z + m4.w*h4.w;
            }
        }
#pragma unroll
        for (int tt=0; tt<8; tt++){
            float v = acc[tt];
#pragma unroll
            for (int o=16;o>0;o>>=1) v += __shfl_xor_sync(0xffffffffu, v, o);
            if (lane == 0) sc[tt][s] = v * scale;
        }
    }
    __syncthreads();
    {
        int tt = w;
        float vals[4], m = -1e30f;
#pragma unroll
        for (int q=0;q<4;q++){ vals[q] = sc[tt][lane + q*32]; m = fmaxf(m, vals[q]); }
#pragma unroll
        for (int o=16;o>0;o>>=1) m = fmaxf(m, __shfl_xor_sync(0xffffffffu, m, o));
        float ssum = 0.f;
#pragma unroll
        for (int q=0;q<4;q++){ vals[q] = __expf(vals[q]-m); ssum += vals[q]; }
#pragma unroll
        for (int o=16;o>0;o>>=1) ssum += __shfl_xor_sync(0xffffffffu, ssum, o);
        float inv = 1.f/ssum;
#pragma unroll
        for (int q=0;q<4;q++) sc[tt][lane + q*32] = vals[q]*inv;
    }
    __syncthreads();
    {
        int d0 = tid*2;
        float acc[8][2];
#pragma unroll
        for (int tt=0;tt<8;tt++){ acc[tt][0]=0.f; acc[tt][1]=0.f; }
        for (int s=0; s<Ss; s++){
            float2 m2 = *(const float2*)(d_mem + (b*Ss + s)*DDEC + d0);
#pragma unroll
            for (int tt=0;tt<8;tt++){
                float p = sc[tt][s];
                acc[tt][0] += p*m2.x; acc[tt][1] += p*m2.y;
            }
        }
#pragma unroll
        for (int tt=0;tt<8;tt++){
            int rr = (t0+tt)*Bb + b;
            float2 v; v.x = acc[tt][0]; v.y = acc[tt][1];
            *(float2*)&d_FFN[rr*(2*DDEC) + DDEC + d0] = v;
        }
    }
    for (int i = tid; i < 8*512; i += 256){
        int tt = i >> 9, d = i & 511;
        int rr = (t0+tt)*Bb + b;
        d_FFN[rr*(2*DDEC) + d] = hs[tt][d];
    }
}

// ---------------- launcher ----------------
static inline void set_pdl(cudaLaunchConfig_t &cfg, cudaLaunchAttribute *attr,
                           dim3 g, dim3 b){
    cfg.gridDim = g; cfg.blockDim = b;
    cfg.dynamicSmemBytes = 0;
    cfg.stream = 0;
    attr[0].id = cudaLaunchAttributeProgrammaticStreamSerialization;
    attr[0].val.programmaticStreamSerializationAllowed = 1;
    cfg.attrs = attr;
    cfg.numAttrs = 1;
}

extern "C" void kernel_launch(void* const* d_in, const int* in_sizes, int n_in,
                              void* d_out, int out_size)
{
    const int*   inp        = (const int*)  d_in[0];
    const int*   label_i    = (const int*)  d_in[1];
    const int*   x          = (const int*)  d_in[2];
    const int*   label      = (const int*)  d_in[3];
    const float* start_emb  = (const float*)d_in[4];
    const float* tok_emb    = (const float*)d_in[5];
    const float* enc_style  = (const float*)d_in[6];
    const float* style_emb  = (const float*)d_in[7];
    const float* Wih_f      = (const float*)d_in[8];
    const float* Whh_f      = (const float*)d_in[9];
    const float* bih_f      = (const float*)d_in[10];
    const float* bhh_f      = (const float*)d_in[11];
    const float* Wih_b      = (const float*)d_in[12];
    const float* Whh_b      = (const float*)d_in[13];
    const float* bih_b      = (const float*)d_in[14];
    const float* bhh_b      = (const float*)d_in[15];
    const float* Wih_d      = (const float*)d_in[16];
    const float* Whh_d      = (const float*)d_in[17];
    const float* bih_d      = (const float*)d_in[18];
    const float* bhh_d      = (const float*)d_in[19];
    const float* W_tr       = (const float*)d_in[20];
    const float* W_f1       = (const float*)d_in[21];
    const float* b_f1       = (const float*)d_in[22];
    const float* W_f2       = (const float*)d_in[23];
    float* out = (float*)d_out;

    float *embS, *decin, *XGf, *XGb, *XGd, *hf, *hb, *H, *ccat, *decpart, *encpart, *FFN, *HID;
    __half *Wf16, *HIDH;
    cudaGetSymbolAddress((void**)&embS,   d_embS);
    cudaGetSymbolAddress((void**)&decin,  d_decin);
    cudaGetSymbolAddress((void**)&XGf,    d_XGf);
    cudaGetSymbolAddress((void**)&XGb,    d_XGb);
    cudaGetSymbolAddress((void**)&XGd,    d_XGd);
    cudaGetSymbolAddress((void**)&hf,     d_hf);
    cudaGetSymbolAddress((void**)&hb,     d_hb);
    cudaGetSymbolAddress((void**)&H,      d_H);
    cudaGetSymbolAddress((void**)&ccat,   d_ccat);
    cudaGetSymbolAddress((void**)&decpart,d_decpart);
    cudaGetSymbolAddress((void**)&encpart,d_encpart);
    cudaGetSymbolAddress((void**)&FFN,    d_FFN);
    cudaGetSymbolAddress((void**)&HID,    d_HID);
    cudaGetSymbolAddress((void**)&Wf16,   d_Wf16);
    cudaGetSymbolAddress((void**)&HIDH,   d_HIDH);

    cudaFuncSetAttribute(f2_mma, cudaFuncAttributeMaxDynamicSharedMemorySize, F2_SMEM);

    // prep
    p_emb  <<<2048,256>>>(inp, tok_emb);
    p_decin<<<2048,256>>>(x, tok_emb, start_emb);
    p_init <<<192,256>>>(label_i, label, enc_style, style_emb);
    conv_w16<<<64000,256>>>(W_f2, Wf16, Vv*DDEC);

    // batched x-part of all LSTM gates (biases folded in)
    gemm_nt<<<dim3( 8,32),256>>>(embS,  Wih_f, XGf, 4096,1024, 128, bih_f, bhh_f, 0,0);
    gemm_nt<<<dim3( 8,32),256>>>(embS,  Wih_b, XGb, 4096,1024, 128, bih_b, bhh_b, 0,1);
    gemm_nt<<<dim3(16,32),256>>>(decin, Wih_d, XGd, 4096,2048, 128, bih_d, bhh_d, 0,0);

    // encoder recurrence (fwd + bwd fused per step), K-split x4, PDL-chained
    {
        cudaLaunchConfig_t cfg; cudaLaunchAttribute attr[1];
        for (int t = 0; t < Ss; t++){
            set_pdl(cfg, attr, dim3(16,4,2), dim3(128));
            cudaLaunchKernelEx(&cfg, lstm_hgemm,
                (const float*)(hf + t*Bb*DENC), (const float*)(hb + t*Bb*DENC),
                Whh_f, Whh_b, encpart, (int)(4*DENC), (int)DENC, 4);
            set_pdl(cfg, attr, dim3(64), dim3(256));
            cudaLaunchKernelEx(&cfg, enc_cell, t);
        }
    }
    mem_assemble<<<8192,256>>>();

    // c_t = lrelu(concat(cf,cb) @ W_tr^T)
    ccat_build<<<64,256>>>();
    lstm_hgemm<<<dim3(8,4,1),128>>>(ccat, nullptr, W_tr, nullptr, decpart, DDEC, DDEC, 4);
    ct_combine<<<64,256>>>();

    // decoder recurrence, K-split x8, PDL-chained
    {
        cudaLaunchConfig_t cfg; cudaLaunchAttribute attr[1];
        for (int t = 0; t < Tt; t++){
            set_pdl(cfg, attr, dim3(32,8,1), dim3(128));
            cudaLaunchKernelEx(&cfg, lstm_hgemm,
                (const float*)(H + t*Bb*DDEC), (const float*)nullptr,
                Whh_d, (const float*)nullptr, decpart, (int)(4*DDEC), (int)DDEC, 8);
            set_pdl(cfg, attr, dim3(64), dim3(256));
            cudaLaunchKernelEx(&cfg, dec_cell, t);
        }
    }

    // batched attention -> FFN input
    attn_kernel<<<dim3(32,16),256>>>();

    // F1: lrelu(FFN @ W_f1^T + b_f1)
    gemm_nt<<<dim3(4,32),256>>>(FFN, W_f1, HID, 4096, 512, 1024, b_f1, nullptr, 1,0);
    conv_w16<<<8192,256>>>(HID, HIDH, Tt*Bb*DDEC);

    // F2 on tensor cores: single-pass fp16, remapped to [B,T,V]
    f2_mma<<<dim3(32,125), 256, F2_SMEM>>>(HIDH, Wf16, out);
}

// round 17
// speedup vs baseline: 2.3514x; 1.4739x over previous
#include <cuda_runtime.h>
#include <cuda_bf16.h>
#include <cuda_fp16.h>
#include <cstdint>

#define Bb 32
#define Ss 128
#define Tt 128
#define DEMB 128
#define DENC 256
#define DDEC 512
#define Vv 32000

// ---------------- scratch (device globals; no runtime allocation) ----------------
__device__ float d_embS [Ss*Bb*DEMB];
__device__ float d_decin[Tt*Bb*DEMB];
__device__ float d_XGf  [Ss*Bb*4*DENC];
__device__ float d_XGb  [Ss*Bb*4*DENC];
__device__ float d_XGd  [Tt*Bb*4*DDEC];
__device__ float d_hf   [(Ss+1)*Bb*DENC];
__device__ float d_hb   [(Ss+1)*Bb*DENC];
__device__ float d_cf   [2*Bb*DENC];
__device__ float d_cb   [2*Bb*DENC];
__device__ float d_encpart[2*4*Bb*4*DENC];     // [dir][ks(4)][b][1024]
__device__ float d_mem  [Bb*Ss*2*DENC];
__device__ float d_ccat [Bb*2*DENC];
__device__ float d_H    [(Tt+1)*Bb*DDEC];
__device__ float d_cd   [2*Bb*DDEC];
__device__ float d_decpart[8*Bb*4*DDEC];       // [ks(8)][b][2048]; also reused by ct path
__device__ float d_FFN  [Tt*Bb*2*DDEC];
__device__ float d_HID  [Tt*Bb*DDEC];
// fp16 operands for tensor-core F2
__device__ __half d_Wf16 [Vv*DDEC];
__device__ __half d_HIDH [Tt*Bb*DDEC];

// ---------------- helpers ----------------
__device__ __forceinline__ float lrelu_f(float x){ return x >= 0.f ? x : 0.1f*x; }
__device__ __forceinline__ float sigm_f (float x){ return 1.f/(1.f+__expf(-x)); }
__device__ __forceinline__ float tanh_f (float x){
    float ax = fabsf(x);
    float e  = __expf(-2.f*ax);
    float r  = (1.f-e)/(1.f+e);
    return x >= 0.f ? r : -r;
}
__device__ __forceinline__ unsigned long long dup2(float a){
    unsigned long long r;
    asm("mov.b64 %0, {%1, %1};" : "=l"(r) : "f"(a));
    return r;
}
__device__ __forceinline__ void fma2(unsigned long long &c, unsigned long long a, unsigned long long w){
    asm("fma.rn.f32x2 %0, %1, %2, %0;" : "+l"(c) : "l"(a), "l"(w));
}
union F4U { float4 f; unsigned long long u[2]; };
union U64F2 { unsigned long long u; float2 f; };

__device__ __forceinline__ uint32_t smem_u32(const void* p){
    uint32_t a; asm("{ .reg .u64 t; cvta.to.shared.u64 t, %1; cvt.u32.u64 %0, t; }" : "=r"(a) : "l"(p));
    return a;
}
__device__ __forceinline__ void cp16(uint32_t saddr, const void* gaddr){
    asm volatile("cp.async.cg.shared.global [%0], [%1], 16;" :: "r"(saddr), "l"(gaddr));
}
__device__ __forceinline__ void ldm_x4(uint32_t addr, uint32_t &r0, uint32_t &r1, uint32_t &r2, uint32_t &r3){
    asm volatile("ldmatrix.sync.aligned.m8n8.x4.shared.b16 {%0,%1,%2,%3}, [%4];"
                 : "=r"(r0), "=r"(r1), "=r"(r2), "=r"(r3) : "r"(addr));
}
__device__ __forceinline__ void mma16816h(float* c, uint32_t a0, uint32_t a1, uint32_t a2, uint32_t a3,
                                          uint32_t b0, uint32_t b1){
    asm volatile("mma.sync.aligned.m16n8k16.row.col.f32.f16.f16.f32 "
                 "{%0,%1,%2,%3}, {%4,%5,%6,%7}, {%8,%9}, {%0,%1,%2,%3};"
                 : "+f"(c[0]), "+f"(c[1]), "+f"(c[2]), "+f"(c[3])
                 : "r"(a0), "r"(a1), "r"(a2), "r"(a3), "r"(b0), "r"(b1));
}

// ---------------- prep kernels ----------------
__global__ void p_emb(const int* __restrict__ inp, const float* __restrict__ tok_emb){
    int idx = blockIdx.x*256 + threadIdx.x;
    int sb = idx >> 7, d = idx & 127;
    int s = sb >> 5, b = sb & 31;
    d_embS[idx] = tok_emb[inp[b*Ss + s]*DEMB + d];
}
__global__ void p_decin(const int* __restrict__ x, const float* __restrict__ tok_emb,
                        const float* __restrict__ start_emb){
    int idx = blockIdx.x*256 + threadIdx.x;
    int tb = idx >> 7, d = idx & 127;
    int t = tb >> 5, b = tb & 31;
    d_decin[idx] = (t == 0) ? start_emb[d] : tok_emb[x[b*Tt + (t-1)]*DEMB + d];
}
__global__ void p_init(const int* __restrict__ label_i, const int* __restrict__ label,
                       const float* __restrict__ enc_style_emb, const float* __restrict__ style_emb){
    int idx = blockIdx.x*256 + threadIdx.x;
    if (idx < 16384){
        int dir = idx >> 13, r = idx & 8191;
        int b = r >> 8, j = r & 255;
        float v = enc_style_emb[label_i[b]*(2*DENC) + dir*DENC + j];
        (dir ? d_hb : d_hf)[b*DENC + j] = v;
    } else if (idx < 32768){
        int r = idx - 16384;
        int dir = r >> 13; r &= 8191;
        (dir ? d_cb : d_cf)[r] = 0.f;
    } else {
        int r = idx - 32768;
        int b = r >> 9, j = r & 511;
        d_H[b*DDEC + j] = style_emb[label[b]*DDEC + j];
    }
}
__global__ void conv_w16(const float* __restrict__ src, __half* __restrict__ dst, int n){
    int i = blockIdx.x*256 + threadIdx.x;
    if (i < n) dst[i] = __float2half_rn(src[i]);
}

// ---------------- fp32 GEMM (XG / F1): C = A @ W^T ----------------
__global__ void __launch_bounds__(256) gemm_nt(
    const float* __restrict__ A, const float* __restrict__ W, float* __restrict__ C,
    int M, int N, int K,
    const float* __restrict__ bias1, const float* __restrict__ bias2,
    int act, int remapA)
{
    __shared__ float As[8][128];
    __shared__ float Bs[8][128];
    int tid = threadIdx.x;
    int bm = blockIdx.y * 128, bn = blockIdx.x * 128;
    int lr = tid >> 1;
    int lc = (tid & 1) << 2;
    int arow = bm + lr;
    if (remapA) arow = ((Ss-1 - (arow >> 5)) << 5) | (arow & 31);
    const float* Aptr = A + arow*K + lc;
    const float* Wptr = W + (bn + lr)*K + lc;

    int m0 = (tid >> 4) << 3;
    int n0 = (tid & 15) << 3;
    unsigned long long acc[8][4];
#pragma unroll
    for (int i=0;i<8;i++)
#pragma unroll
        for (int j=0;j<4;j++) acc[i][j] = 0ull;

    for (int k0 = 0; k0 < K; k0 += 8){
        float4 a4 = *(const float4*)(Aptr + k0);
        float4 w4 = *(const float4*)(Wptr + k0);
        As[lc+0][lr]=a4.x; As[lc+1][lr]=a4.y; As[lc+2][lr]=a4.z; As[lc+3][lr]=a4.w;
        Bs[lc+0][lr]=w4.x; Bs[lc+1][lr]=w4.y; Bs[lc+2][lr]=w4.z; Bs[lc+3][lr]=w4.w;
        __syncthreads();
#pragma unroll
        for (int kk=0; kk<8; kk++){
            float4 a0 = *(const float4*)&As[kk][m0];
            float4 a1 = *(const float4*)&As[kk][m0+4];
            F4U ub0, ub1;
            ub0.f = *(const float4*)&Bs[kk][n0];
            ub1.f = *(const float4*)&Bs[kk][n0+4];
            unsigned long long w0=ub0.u[0], w1=ub0.u[1], w2=ub1.u[0], w3=ub1.u[1];
            float av[8] = {a0.x,a0.y,a0.z,a0.w,a1.x,a1.y,a1.z,a1.w};
#pragma unroll
            for (int i=0;i<8;i++){
                unsigned long long ad = dup2(av[i]);
                fma2(acc[i][0], ad, w0);
                fma2(acc[i][1], ad, w1);
                fma2(acc[i][2], ad, w2);
                fma2(acc[i][3], ad, w3);
            }
        }
        __syncthreads();
    }
#pragma unroll
    for (int i=0;i<8;i++){
        int mg = bm + m0 + i;
#pragma unroll
        for (int j=0;j<4;j++){
            U64F2 u; u.u = acc[i][j];
            float2 v = u.f;
            int ng = bn + n0 + 2*j;
            if (bias1){ v.x += bias1[ng]; v.y += bias1[ng+1]; }
            if (bias2){ v.x += bias2[ng]; v.y += bias2[ng+1]; }
            if (act){ v.x = lrelu_f(v.x); v.y = lrelu_f(v.y); }
            *(float2*)&C[mg*N + ng] = v;
        }
    }
}

// ---------------- mma.sync fp16 single-pass F2 GEMM ----------------
#define F2_NCHUNK 16
#define F2_ASTG   (128*40*2)
#define F2_BSTG   (256*40*2)
#define F2_STG    (F2_ASTG + F2_BSTG)
#define F2_SMEM   (3*F2_STG)
__global__ void __launch_bounds__(256) f2_mma(
    const __half* __restrict__ AH, const __half* __restrict__ Bg, float* __restrict__ out)
{
    extern __shared__ __half sm[];
    int tid = threadIdx.x;
    int wid = tid >> 5, lane = tid & 31;
    int warp_m = wid & 1, warp_n = wid >> 1;
    int bm = blockIdx.x * 128;
    int bn = blockIdx.y * 256;
    uint32_t sbase = smem_u32(sm);

    float acc[4][8][4];
#pragma unroll
    for (int i=0;i<4;i++)
#pragma unroll
        for (int j=0;j<8;j++)
#pragma unroll
            for (int q=0;q<4;q++) acc[i][j][q] = 0.f;

    auto load_chunk = [&](int c, int s){
        int k0 = c * 32;
        uint32_t base = sbase + (uint32_t)s * F2_STG;
#pragma unroll
        for (int q=0; q<2; q++){
            int i = q*256 + tid;
            int row = i >> 2, sg = i & 3;
            cp16(base + (uint32_t)(row*80 + sg*16), AH + (size_t)(bm + row)*DDEC + k0 + sg*8);
        }
#pragma unroll
        for (int q=0; q<4; q++){
            int i = q*256 + tid;
            int row = i >> 2, sg = i & 3;
            cp16(base + F2_ASTG + (uint32_t)(row*80 + sg*16),
                 Bg + (size_t)(bn + row)*DDEC + k0 + sg*8);
        }
        asm volatile("cp.async.commit_group;" ::: "memory");
    };

    load_chunk(0, 0);
    load_chunk(1, 1);

    int ld_s = 2, cs = 0;
    for (int c = 0; c < F2_NCHUNK; c++){
        if (c < F2_NCHUNK-1) asm volatile("cp.async.wait_group 1;" ::: "memory");
        else                 asm volatile("cp.async.wait_group 0;" ::: "memory");
        __syncthreads();
        if (c + 2 < F2_NCHUNK){
            load_chunk(c+2, ld_s);
            ld_s++; if (ld_s == 3) ld_s = 0;
        }
        uint32_t baseA = sbase + (uint32_t)cs * F2_STG;
        uint32_t baseB = baseA + F2_ASTG;
#pragma unroll
        for (int ks = 0; ks < 2; ks++){
            int kc = ks * 16;
            int g = lane >> 3, r = lane & 7;
            uint32_t af[4][4];
#pragma unroll
            for (int mt=0; mt<4; mt++){
                int row = warp_m*64 + mt*16 + (g & 1)*8 + r;
                int col = kc + (g >> 1)*8;
                ldm_x4(baseA + (uint32_t)(row*80 + col*2), af[mt][0], af[mt][1], af[mt][2], af[mt][3]);
            }
            uint32_t bf[8][2];
#pragma unroll
            for (int j=0; j<4; j++){
                int nrow = warp_n*64 + (j*2 + (g >> 1))*8 + r;
                int col = kc + (g & 1)*8;
                ldm_x4(baseB + (uint32_t)(nrow*80 + col*2),
                       bf[j*2][0], bf[j*2][1], bf[j*2+1][0], bf[j*2+1][1]);
            }
#pragma unroll
            for (int mt=0; mt<4; mt++)
#pragma unroll
                for (int nt=0; nt<8; nt++)
                    mma16816h(acc[mt][nt], af[mt][0], af[mt][1], af[mt][2], af[mt][3],
                              bf[nt][0], bf[nt][1]);
        }
        __syncthreads();
        cs++; if (cs == 3) cs = 0;
    }

#pragma unroll
    for (int mt=0; mt<4; mt++){
#pragma unroll
        for (int half=0; half<2; half++){
            int mg = bm + warp_m*64 + mt*16 + (lane >> 2) + half*8;
            int t = mg >> 5, b = mg & 31;
            float* dst = out + (size_t)(b*Tt + t)*Vv + bn + warp_n*64;
#pragma unroll
            for (int nt=0; nt<8; nt++){
                float2 v;
                v.x = acc[mt][nt][half*2+0];
                v.y = acc[mt][nt][half*2+1];
                *(float2*)&dst[nt*8 + 2*(lane & 3)] = v;
            }
        }
    }
}

// ---------------- small-M recurrence GEMM (f32x2-packed inner loop) ----------------
__global__ void __launch_bounds__(128) lstm_hgemm(
    const float* __restrict__ H0, const float* __restrict__ H1,
    const float* __restrict__ W0, const float* __restrict__ W1,
    float* __restrict__ part, int Ntot, int KH, int KS)
{
    int dir = blockIdx.z;
    const float* Hd = dir ? H1 : H0;
    const float* Wd = dir ? W1 : W0;
    int n0blk = blockIdx.x * 64;
    int ksub = KH / KS;
    int kbase = blockIdx.y * ksub;
    __shared__ float As[32][36];
    __shared__ float Ws[32][68];
    int tid = threadIdx.x;
    int bth = (tid >> 4) << 2;
    int nth = (tid & 15) << 2;
    unsigned long long accp[2][4];
#pragma unroll
    for (int p=0;p<2;p++)
#pragma unroll
        for (int j=0;j<4;j++) accp[p][j] = 0ull;

    for (int k0 = 0; k0 < ksub; k0 += 32){
#pragma unroll
        for (int q=0;q<2;q++){
            int f4 = tid*2 + q;
            int bb = f4 >> 3, kq = (f4 & 7) << 2;
            float4 v = *(const float4*)(Hd + bb*KH + kbase + k0 + kq);
            As[kq+0][bb]=v.x; As[kq+1][bb]=v.y; As[kq+2][bb]=v.z; As[kq+3][bb]=v.w;
        }
#pragma unroll
        for (int q=0;q<4;q++){
            int f4 = tid*4 + q;
            int nn = f4 >> 3, kq = (f4 & 7) << 2;
            float4 v = *(const float4*)(Wd + (n0blk+nn)*KH + kbase + k0 + kq);
            Ws[kq+0][nn]=v.x; Ws[kq+1][nn]=v.y; Ws[kq+2][nn]=v.z; Ws[kq+3][nn]=v.w;
        }
        __syncthreads();
#pragma unroll
        for (int kk=0; kk<32; kk++){
            F4U a4; a4.f = *(const float4*)&As[kk][bth];
            float4 w4 = *(const float4*)&Ws[kk][nth];
            unsigned long long wd0 = dup2(w4.x);
            unsigned long long wd1 = dup2(w4.y);
            unsigned long long wd2 = dup2(w4.z);
            unsigned long long wd3 = dup2(w4.w);
            fma2(accp[0][0], a4.u[0], wd0);
            fma2(accp[0][1], a4.u[0], wd1);
            fma2(accp[0][2], a4.u[0], wd2);
            fma2(accp[0][3], a4.u[0], wd3);
            fma2(accp[1][0], a4.u[1], wd0);
            fma2(accp[1][1], a4.u[1], wd1);
            fma2(accp[1][2], a4.u[1], wd2);
            fma2(accp[1][3], a4.u[1], wd3);
        }
        __syncthreads();
    }
    float* pbase = part + ((dir*KS + blockIdx.y)*32)*Ntot;
#pragma unroll
    for (int p=0;p<2;p++){
        U64F2 c0,c1,c2,c3;
        c0.u=accp[p][0]; c1.u=accp[p][1]; c2.u=accp[p][2]; c3.u=accp[p][3];
        float4 vlo; vlo.x=c0.f.x; vlo.y=c1.f.x; vlo.z=c2.f.x; vlo.w=c3.f.x;
        float4 vhi; vhi.x=c0.f.y; vhi.y=c1.f.y; vhi.z=c2.f.y; vhi.w=c3.f.y;
        *(float4*)&pbase[(bth+2*p+0)*Ntot + n0blk + nth] = vlo;
        *(float4*)&pbase[(bth+2*p+1)*Ntot + n0blk + nth] = vhi;
    }
}

// ---------------- cell updates ----------------
__global__ void enc_cell(int t){
    int idx = blockIdx.x*256 + threadIdx.x;
    int dir = idx >> 13, r = idx & 8191;
    int b = r >> 8, j = r & 255;
    const float* XG = dir ? d_XGb : d_XGf;
    float g[4];
#pragma unroll
    for (int gt=0; gt<4; gt++){
        int n = gt*DENC + j;
        float v = XG[(t*Bb + b)*(4*DENC) + n];
#pragma unroll
        for (int ks=0; ks<4; ks++)
            v += d_encpart[((dir*4+ks)*Bb + b)*(4*DENC) + n];
        g[gt] = v;
    }
    float* cbuf = dir ? d_cb : d_cf;
    float cold = cbuf[(t&1)*Bb*DENC + b*DENC + j];
    float i_ = sigm_f(g[0]), f_ = sigm_f(g[1]), gg = tanh_f(g[2]), o_ = sigm_f(g[3]);
    float cn = f_*cold + i_*gg;
    float hn = o_*tanh_f(cn);
    cbuf[((t+1)&1)*Bb*DENC + b*DENC + j] = cn;
    (dir ? d_hb : d_hf)[((t+1)*Bb + b)*DENC + j] = hn;
}
__global__ void dec_cell(int t){
    int idx = blockIdx.x*256 + threadIdx.x;
    int b = idx >> 9, j = idx & 511;
    float g[4];
#pragma unroll
    for (int gt=0; gt<4; gt++){
        int n = gt*DDEC + j;
        float v = d_XGd[(t*Bb + b)*(4*DDEC) + n];
#pragma unroll
        for (int ky=0; ky<8; ky++) v += d_decpart[(ky*Bb + b)*(4*DDEC) + n];
        g[gt] = v;
    }
    float cold = d_cd[(t&1)*Bb*DDEC + b*DDEC + j];
    float i_ = sigm_f(g[0]), f_ = sigm_f(g[1]), gg = tanh_f(g[2]), o_ = sigm_f(g[3]);
    float cn = f_*cold + i_*gg;
    float hn = o_*tanh_f(cn);
    d_cd[((t+1)&1)*Bb*DDEC + b*DDEC + j] = cn;
    d_H[((t+1)*Bb + b)*DDEC + j] = hn;
}

// ---------------- misc glue ----------------
__global__ void mem_assemble(){
    int idx = blockIdx.x*256 + threadIdx.x;
    int b = idx >> 16, r = idx & 65535;
    int s = r >> 9, d = r & 511;
    float v;
    if (d < DENC) v = d_hf[((s+1)*Bb + b)*DENC + d];
    else          v = d_hb[((Ss - s)*Bb + b)*DENC + (d - DENC)];
    d_mem[idx] = v;
}
__global__ void ccat_build(){
    int idx = blockIdx.x*256 + threadIdx.x;
    int b = idx >> 9, j = idx & 511;
    d_ccat[idx] = (j < DENC) ? d_cf[b*DENC + j] : d_cb[b*DENC + (j - DENC)];
}
__global__ void ct_combine(){
    int idx = blockIdx.x*256 + threadIdx.x;
    int b = idx >> 9, j = idx & 511;
    float v = 0.f;
#pragma unroll
    for (int ky=0; ky<4; ky++) v += d_decpart[(ky*Bb + b)*DDEC + j];
    d_cd[b*DDEC + j] = lrelu_f(v);
}

// ---------------- attention ----------------
__global__ void __launch_bounds__(256) attn_kernel(){
    int b  = blockIdx.x;
    int t0 = blockIdx.y * 8;
    __shared__ float hs[8][512];
    __shared__ float sc[8][128];
    int tid = threadIdx.x;
    for (int i = tid; i < 8*512; i += 256){
        int tt = i >> 9, d = i & 511;
        hs[tt][d] = d_H[((t0 + tt + 1)*Bb + b)*DDEC + d];
    }
    __syncthreads();
    int w = tid >> 5, lane = tid & 31;
    const float scale = 0.04419417382415922f;
    for (int si = 0; si < 16; si++){
        int s = w*16 + si;
        const float* mrow = d_mem + (b*Ss + s)*DDEC;
        float acc[8] = {0,0,0,0,0,0,0,0};
#pragma unroll
        for (int q=0; q<4; q++){
            int d = q*128 + lane*4;
            float4 m4 = *(const float4*)(mrow + d);
#pragma unroll
            for (int tt=0; tt<8; tt++){
                float4 h4 = *(const float4*)&hs[tt][d];
                acc[tt] += m4.x*h4.x + m4.y*h4.y + m4.z*h4.z + m4.w*h4.w;
            }
        }
#pragma unroll
        for (int tt=0; tt<8; tt++){
            float v = acc[tt];
#pragma unroll
            for (int o=16;o>0;o>>=1) v += __shfl_xor_sync(0xffffffffu, v, o);
            if (lane == 0) sc[tt][s] = v * scale;
        }
    }
    __syncthreads();
    {
        int tt = w;
        float vals[4], m = -1e30f;
#pragma unroll
        for (int q=0;q<4;q++){ vals[q] = sc[tt][lane + q*32]; m = fmaxf(m, vals[q]); }
#pragma unroll
        for (int o=16;o>0;o>>=1) m = fmaxf(m, __shfl_xor_sync(0xffffffffu, m, o));
        float ssum = 0.f;
#pragma unroll
        for (int q=0;q<4;q++){ vals[q] = __expf(vals[q]-m); ssum += vals[q]; }
#pragma unroll
        for (int o=16;o>0;o>>=1) ssum += __shfl_xor_sync(0xffffffffu, ssum, o);
        float inv = 1.f/ssum;
#pragma unroll
        for (int q=0;q<4;q++) sc[tt][lane + q*32] = vals[q]*inv;
    }
    __syncthreads();
    {
        int d0 = tid*2;
        float acc[8][2];
#pragma unroll
        for (int tt=0;tt<8;tt++){ acc[tt][0]=0.f; acc[tt][1]=0.f; }
        for (int s=0; s<Ss; s++){
            float2 m2 = *(const float2*)(d_mem + (b*Ss + s)*DDEC + d0);
#pragma unroll
            for (int tt=0;tt<8;tt++){
                float p = sc[tt][s];
                acc[tt][0] += p*m2.x; acc[tt][1] += p*m2.y;
            }
        }
#pragma unroll
        for (int tt=0;tt<8;tt++){
            int rr = (t0+tt)*Bb + b;
            float2 v; v.x = acc[tt][0]; v.y = acc[tt][1];
            *(float2*)&d_FFN[rr*(2*DDEC) + DDEC + d0] = v;
        }
    }
    for (int i = tid; i < 8*512; i += 256){
        int tt = i >> 9, d = i & 511;
        int rr = (t0+tt)*Bb + b;
        d_FFN[rr*(2*DDEC) + d] = hs[tt][d];
    }
}

// ---------------- launcher ----------------
extern "C" void kernel_launch(void* const* d_in, const int* in_sizes, int n_in,
                              void* d_out, int out_size)
{
    const int*   inp        = (const int*)  d_in[0];
    const int*   label_i    = (const int*)  d_in[1];
    const int*   x          = (const int*)  d_in[2];
    const int*   label      = (const int*)  d_in[3];
    const float* start_emb  = (const float*)d_in[4];
    const float* tok_emb    = (const float*)d_in[5];
    const float* enc_style  = (const float*)d_in[6];
    const float* style_emb  = (const float*)d_in[7];
    const float* Wih_f      = (const float*)d_in[8];
    const float* Whh_f      = (const float*)d_in[9];
    const float* bih_f      = (const float*)d_in[10];
    const float* bhh_f      = (const float*)d_in[11];
    const float* Wih_b      = (const float*)d_in[12];
    const float* Whh_b      = (const float*)d_in[13];
    const float* bih_b      = (const float*)d_in[14];
    const float* bhh_b      = (const float*)d_in[15];
    const float* Wih_d      = (const float*)d_in[16];
    const float* Whh_d      = (const float*)d_in[17];
    const float* bih_d      = (const float*)d_in[18];
    const float* bhh_d      = (const float*)d_in[19];
    const float* W_tr       = (const float*)d_in[20];
    const float* W_f1       = (const float*)d_in[21];
    const float* b_f1       = (const float*)d_in[22];
    const float* W_f2       = (const float*)d_in[23];
    float* out = (float*)d_out;

    float *embS, *decin, *XGf, *XGb, *XGd, *hf, *hb, *H, *ccat, *decpart, *encpart, *FFN, *HID;
    __half *Wf16, *HIDH;
    cudaGetSymbolAddress((void**)&embS,   d_embS);
    cudaGetSymbolAddress((void**)&decin,  d_decin);
    cudaGetSymbolAddress((void**)&XGf,    d_XGf);
    cudaGetSymbolAddress((void**)&XGb,    d_XGb);
    cudaGetSymbolAddress((void**)&XGd,    d_XGd);
    cudaGetSymbolAddress((void**)&hf,     d_hf);
    cudaGetSymbolAddress((void**)&hb,     d_hb);
    cudaGetSymbolAddress((void**)&H,      d_H);
    cudaGetSymbolAddress((void**)&ccat,   d_ccat);
    cudaGetSymbolAddress((void**)&decpart,d_decpart);
    cudaGetSymbolAddress((void**)&encpart,d_encpart);
    cudaGetSymbolAddress((void**)&FFN,    d_FFN);
    cudaGetSymbolAddress((void**)&HID,    d_HID);
    cudaGetSymbolAddress((void**)&Wf16,   d_Wf16);
    cudaGetSymbolAddress((void**)&HIDH,   d_HIDH);

    static cudaStream_t s2 = nullptr;
    static cudaEvent_t evA = nullptr, evB = nullptr, evC = nullptr, evD = nullptr;
    if (!s2){
        cudaStreamCreate(&s2);
        cudaEventCreateWithFlags(&evA, cudaEventDisableTiming);
        cudaEventCreateWithFlags(&evB, cudaEventDisableTiming);
        cudaEventCreateWithFlags(&evC, cudaEventDisableTiming);
        cudaEventCreateWithFlags(&evD, cudaEventDisableTiming);
        cudaFuncSetAttribute(f2_mma, cudaFuncAttributeMaxDynamicSharedMemorySize, F2_SMEM);
    }

    // prep (stream 0)
    p_emb  <<<2048,256>>>(inp, tok_emb);
    p_decin<<<2048,256>>>(x, tok_emb, start_emb);
    p_init <<<192,256>>>(label_i, label, enc_style, style_emb);

    // fork: W_f2 conversion + XGd gemm run on s2, hidden under the encoder chain
    cudaEventRecord(evA, 0);
    cudaStreamWaitEvent(s2, evA, 0);
    conv_w16<<<64000,256,0,s2>>>(W_f2, Wf16, Vv*DDEC);
    gemm_nt<<<dim3(16,32),256,0,s2>>>(decin, Wih_d, XGd, 4096,2048, 128, bih_d, bhh_d, 0,0);
    cudaEventRecord(evB, s2);

    // x-part of encoder gates (stream 0; encoder chain needs these)
    gemm_nt<<<dim3( 8,32),256>>>(embS,  Wih_f, XGf, 4096,1024, 128, bih_f, bhh_f, 0,0);
    gemm_nt<<<dim3( 8,32),256>>>(embS,  Wih_b, XGb, 4096,1024, 128, bih_b, bhh_b, 0,1);

    // encoder recurrence (fwd + bwd fused per step), K-split x4
    for (int t = 0; t < Ss; t++){
        lstm_hgemm<<<dim3(16,4,2),128>>>(hf + t*Bb*DENC, hb + t*Bb*DENC,
                                         Whh_f, Whh_b, encpart, 4*DENC, DENC, 4);
        enc_cell<<<64,256>>>(t);
    }

    // fork: mem_assemble on s2, hidden under decoder chain
    cudaEventRecord(evC, 0);
    cudaStreamWaitEvent(s2, evC, 0);
    mem_assemble<<<8192,256,0,s2>>>();
    cudaEventRecord(evD, s2);

    // c_t = lrelu(concat(cf,cb) @ W_tr^T)  (stream 0)
    ccat_build<<<64,256>>>();
    lstm_hgemm<<<dim3(8,4,1),128>>>(ccat, nullptr, W_tr, nullptr, decpart, DDEC, DDEC, 4);
    ct_combine<<<64,256>>>();

    // join: decoder needs XGd (evB)
    cudaStreamWaitEvent(0, evB, 0);

    // decoder recurrence, K-split x8
    for (int t = 0; t < Tt; t++){
        lstm_hgemm<<<dim3(32,8,1),128>>>(H + t*Bb*DDEC, nullptr,
                                         Whh_d, nullptr, decpart, 4*DDEC, DDEC, 8);
        dec_cell<<<64,256>>>(t);
    }

    // join: attention needs memory (evD)
    cudaStreamWaitEvent(0, evD, 0);

    // batched attention -> FFN input
    attn_kernel<<<dim3(32,16),256>>>();

    // F1: lrelu(FFN @ W_f1^T + b_f1)
    gemm_nt<<<dim3(4,32),256>>>(FFN, W_f1, HID, 4096, 512, 1024, b_f1, nullptr, 1,0);
    conv_w16<<<8192,256>>>(HID, HIDH, Tt*Bb*DDEC);

    // F2 on tensor cores: single-pass fp16, remapped to [B,T,V]
    f2_mma<<<dim3(32,125), 256, F2_SMEM>>>(HIDH, Wf16, out);
}